// round 14
// baseline (speedup 1.0000x reference)
#include <cuda_runtime.h>
#include <cuda_bf16.h>

#define NA    512
#define Fdim  128
#define FEdim 128
#define HID   256
#define Bb    14
#define BB    196
#define NBdim 7168
#define TP    128          // pairs per CTA
#define NT    256
#define N2PAD 224          // padded GEMM2 N (196 -> 224)

// -------- arch-feature detection: tcgen05 only exists on the 'a' target ----
#if defined(__CUDA_ARCH__) && \
    (defined(__CUDA_ARCH_FEAT_SM103_ALL) || \
     (defined(__CUDA_ARCH_SPECIFIC__) && (__CUDA_ARCH_SPECIFIC__ == 1030)) || \
     (defined(__CUDA_ARCH_FAMILY_SPECIFIC__) && (__CUDA_ARCH_FAMILY_SPECIFIC__ == 1030)))
#define HAS_TC 1
#else
#define HAS_TC 0
#endif

// ---------------- device scratch ----------------
__device__ __align__(16) __nv_bfloat16 g_W1T[HID * 384];     // [256][384]
__device__ __align__(16) __nv_bfloat16 g_W2T[N2PAD * HID];   // [224][256]

// ---------------- smem byte offsets (~104KB -> 2 CTAs/SM) ----------------
#define SM_X0    0         // X chunk buf0  [128][64]bf16 = 16384
#define SM_X1    16384
#define SM_W0    32768     // W1 chunk buf0 [256][64]bf16 = 32768
#define SM_W1    65536     // W1 chunk buf1
#define SM_H     0         // H [128][256]bf16, 4 chunk-blocks of 16384
#define SM_W2    65536     // W2 chunk [224][64]bf16 = 28672, single buf
#define SM_M     0         // sM [128][201] f32 = 102912
#define SM_BARS  102912    // +0 tmem ptr, +8 bar0, +16 bar1
#define SM_B1    102944    // bo1 256 f32
#define SM_B2    103968    // bo2 padded 224 f32
#define SM_IJ    104864    // 128 i + 128 j int
#define SMEM_TOTAL 105984

#define SW(o) ((o) ^ (((o) >> 3) & 0x70))

// idesc: dtype=F32, a=BF16, b=BF16, K-major, M=128
#define IDESC1 ((1u<<4)|(1u<<7)|(1u<<10)|((HID/8)<<17)|((128/16)<<24))    // N=256
#define IDESC2 ((1u<<4)|(1u<<7)|(1u<<10)|((N2PAD/8)<<17)|((128/16)<<24))  // N=224

// ---------------- generic helpers ----------------
__device__ __forceinline__ float silu_f(float x) { return x / (1.0f + __expf(-x)); }
__device__ __forceinline__ unsigned f2bf2(float lo, float hi) {
    __nv_bfloat162 h = __floats2bfloat162_rn(lo, hi);
    return *(unsigned*)&h;
}
__device__ __forceinline__ unsigned smem_u32(const void* p) {
    unsigned a;
    asm("{ .reg .u64 t; cvta.to.shared.u64 t, %1; cvt.u32.u64 %0, t; }" : "=r"(a) : "l"(p));
    return a;
}
__device__ __forceinline__ void cp_async16(unsigned dst, const void* src) {
    asm volatile("cp.async.cg.shared.global [%0], [%1], 16;" :: "r"(dst), "l"(src) : "memory");
}
__device__ __forceinline__ void cp_commit() {
    asm volatile("cp.async.commit_group;" ::: "memory");
}
__device__ __forceinline__ void cp_wait0() {
    asm volatile("cp.async.wait_group 0;" ::: "memory");
}

#if HAS_TC
// ---------------- tcgen05 PTX helpers (only on the 'a' target) ----
__device__ __forceinline__ unsigned long long mk_desc(unsigned addr) {
    const unsigned long long base =
        (2ull << 61) | (1ull << 46) | (64ull << 32) | (1ull << 16);   // SW128, LBO=1, SBO=64
    return base | ((unsigned long long)(addr >> 4) & 0x3FFF);
}
__device__ __forceinline__ void mma_f16_ss(unsigned d, unsigned long long a,
                                           unsigned long long b, unsigned idesc, bool acc) {
    unsigned e = acc ? 1u : 0u;
    asm volatile(
        "{\n\t.reg .pred p;\n\t"
        "setp.ne.u32 p, %5, 0;\n\t"
        "tcgen05.mma.cta_group::1.kind::f16 [%0], %1, %2, %3, {%4,%4,%4,%4}, p;\n\t}"
        :: "r"(d), "l"(a), "l"(b), "r"(idesc), "r"(0u), "r"(e) : "memory");
}
__device__ __forceinline__ void tmem_alloc(unsigned smem_addr, unsigned ncols) {
    asm volatile("tcgen05.alloc.cta_group::1.sync.aligned.shared::cta.b32 [%0], %1;"
                 :: "r"(smem_addr), "r"(ncols) : "memory");
}
__device__ __forceinline__ void tmem_dealloc(unsigned tmem, unsigned ncols) {
    asm volatile("tcgen05.dealloc.cta_group::1.sync.aligned.b32 %0, %1;" :: "r"(tmem), "r"(ncols));
}
__device__ __forceinline__ void tmem_relinquish() {
    asm volatile("tcgen05.relinquish_alloc_permit.cta_group::1.sync.aligned;");
}
__device__ __forceinline__ void mbar_init(unsigned addr, unsigned cnt) {
    asm volatile("mbarrier.init.shared.b64 [%0], %1;" :: "r"(addr), "r"(cnt) : "memory");
}
__device__ __forceinline__ void mbar_wait(unsigned addr, unsigned parity) {
    asm volatile(
        "{\n\t.reg .pred P1;\n\t"
        "W%=:\n\t"
        "mbarrier.try_wait.parity.acquire.cta.shared::cta.b64 P1, [%0], %1, 0x989680;\n\t"
        "@P1 bra.uni D%=;\n\t"
        "bra.uni W%=;\n\t"
        "D%=:\n\t}"
        :: "r"(addr), "r"(parity) : "memory");
}
__device__ __forceinline__ void mma_commit(unsigned bar) {
    asm volatile("tcgen05.commit.cta_group::1.mbarrier::arrive::one.shared::cluster.b64 [%0];"
                 :: "r"(bar) : "memory");
}
__device__ __forceinline__ void fence_async_smem() {
    asm volatile("fence.proxy.async.shared::cta;" ::: "memory");
}
__device__ __forceinline__ void tc_fence_after() {
    asm volatile("tcgen05.fence::after_thread_sync;" ::: "memory");
}
__device__ __forceinline__ void tc_fence_before() {
    asm volatile("tcgen05.fence::before_thread_sync;" ::: "memory");
}
__device__ __forceinline__ void wait_ld() {
    asm volatile("tcgen05.wait::ld.sync.aligned;" ::: "memory");
}
__device__ __forceinline__ void ldtm32(unsigned* r, unsigned addr) {
    asm volatile(
        "tcgen05.ld.sync.aligned.32x32b.x32.b32 "
        "{%0,%1,%2,%3,%4,%5,%6,%7,%8,%9,%10,%11,%12,%13,%14,%15,"
        "%16,%17,%18,%19,%20,%21,%22,%23,%24,%25,%26,%27,%28,%29,%30,%31}, [%32];"
        : "=r"(r[0]),"=r"(r[1]),"=r"(r[2]),"=r"(r[3]),"=r"(r[4]),"=r"(r[5]),"=r"(r[6]),"=r"(r[7]),
          "=r"(r[8]),"=r"(r[9]),"=r"(r[10]),"=r"(r[11]),"=r"(r[12]),"=r"(r[13]),"=r"(r[14]),"=r"(r[15]),
          "=r"(r[16]),"=r"(r[17]),"=r"(r[18]),"=r"(r[19]),"=r"(r[20]),"=r"(r[21]),"=r"(r[22]),"=r"(r[23]),
          "=r"(r[24]),"=r"(r[25]),"=r"(r[26]),"=r"(r[27]),"=r"(r[28]),"=r"(r[29]),"=r"(r[30]),"=r"(r[31])
        : "r"(addr));
}
__device__ __forceinline__ void ldtm4(unsigned& a, unsigned& b, unsigned& c, unsigned& d, unsigned addr) {
    asm volatile("tcgen05.ld.sync.aligned.32x32b.x4.b32 {%0,%1,%2,%3}, [%4];"
                 : "=r"(a), "=r"(b), "=r"(c), "=r"(d) : "r"(addr));
}
#endif  // HAS_TC

// ===========================================================================
// prep: transpose + bf16-convert weights into device scratch
// ===========================================================================
__global__ void prep_kernel(const float* __restrict__ Wo1, const float* __restrict__ Wo2) {
    int stride = gridDim.x * blockDim.x;
    int t = blockIdx.x * blockDim.x + threadIdx.x;
    for (int e = t; e < HID * 384; e += stride) {
        int n = e / 384, k = e - n * 384;
        g_W1T[e] = __float2bfloat16(Wo1[k * HID + n]);
    }
    for (int e = t; e < N2PAD * HID; e += stride) {
        int n = e / HID, k = e - n * HID;
        g_W2T[e] = (n < BB) ? __float2bfloat16(Wo2[k * BB + n]) : __float2bfloat16(0.0f);
    }
}

// ===========================================================================
// Off-diagonal tcgen05 kernel: 128 pairs per CTA, 2 CTAs per SM
// ===========================================================================
__global__ void __launch_bounds__(NT, 2)
off_tc_kernel(const float* __restrict__ nodes, const float* __restrict__ edges,
              const float* __restrict__ overlap,
              const float* __restrict__ bo1, const float* __restrict__ bo2,
              const int* __restrict__ pi, const int* __restrict__ pj,
              float* __restrict__ out)
{
#if HAS_TC
    extern __shared__ char smem[];
    const unsigned sb = smem_u32(smem);
    const int tid = threadIdx.x;
    const int pbase = blockIdx.x * TP;

    int*   sI  = (int*)(smem + SM_IJ);
    int*   sJ  = sI + TP;
    float* sB1 = (float*)(smem + SM_B1);
    float* sB2 = (float*)(smem + SM_B2);

    if (tid < TP) { sI[tid] = pi[pbase + tid]; sJ[tid] = pj[pbase + tid]; }
    sB1[tid] = bo1[tid];
    if (tid < N2PAD) sB2[tid] = (tid < BB) ? bo2[tid] : 0.0f;

    if (tid == 0) {
        mbar_init(sb + SM_BARS + 8, 1);
        mbar_init(sb + SM_BARS + 16, 1);
    }
    if (tid < 32) {
        tmem_alloc(sb + SM_BARS, 256);   // D1 0..255; D2 reuses 0..223
        tmem_relinquish();
    }
    __syncthreads();

    unsigned tmem;
    asm volatile("ld.shared.b32 %0, [%1];" : "=r"(tmem) : "r"(sb + SM_BARS));
    const unsigned bar0 = sb + SM_BARS + 8;
    const unsigned bar1 = sb + SM_BARS + 16;
    int cnt0 = 0, cnt1 = 0;

    // gather mapping: 8 lanes per pair-row segment (coalesced 32B/lane)
    const int gseg = tid & 7;
    const int grow0 = tid >> 3;

    // ---------------- GEMM1: D1[128,256] = X[128,384] @ Wo1, K chunks of 64
    #pragma unroll 1
    for (int c = 0; c < 6; c++) {
        const int b = c & 1;
        if (c >= 2) {
            if (b == 0) { mbar_wait(bar0, cnt0 & 1); cnt0++; }
            else        { mbar_wait(bar1, cnt1 & 1); cnt1++; }
        }
        // W1 chunk [256][64]bf16 -> swizzled smem via cp.async (fire first)
        {
            const unsigned wdst = sb + (b ? SM_W1 : SM_W0);
            #pragma unroll
            for (int t = 0; t < 8; t++) {
                int e = tid + t * NT;         // 0..2047
                int row = e >> 3, g = e & 7;
                cp_async16(wdst + SW(row * 128 + g * 16),
                           g_W1T + (size_t)row * 384 + c * 64 + g * 8);
            }
            cp_commit();
        }
        // X chunk gather+convert -> swizzled smem [128][64]bf16 (coalesced)
        {
            char* xdst = smem + (b ? SM_X1 : SM_X0);
            #pragma unroll
            for (int it = 0; it < 4; it++) {
                const int p = grow0 + it * 32;
                const int xi = sI[p], xj = sJ[p];
                const float* s;
                if (c < 2)      s = nodes + (size_t)xi * Fdim + c * 64;
                else if (c < 4) s = nodes + (size_t)xj * Fdim + (c - 2) * 64;
                else            s = edges + ((size_t)xi * NA + xj) * FEdim + (c - 4) * 64;
                s += gseg * 8;
                float4 v0 = *(const float4*)(s);
                float4 v1 = *(const float4*)(s + 4);
                uint4 w;
                w.x = f2bf2(v0.x, v0.y); w.y = f2bf2(v0.z, v0.w);
                w.z = f2bf2(v1.x, v1.y); w.w = f2bf2(v1.z, v1.w);
                *(uint4*)(xdst + SW(p * 128 + gseg * 16)) = w;
            }
        }
        cp_wait0();
        fence_async_smem();
        __syncthreads();
        if (tid == 0) {
            unsigned long long ad = mk_desc(sb + (b ? SM_X1 : SM_X0));
            unsigned long long bd = mk_desc(sb + (b ? SM_W1 : SM_W0));
            #pragma unroll
            for (int ks = 0; ks < 4; ks++)
                mma_f16_ss(tmem, ad + ks * 2, bd + ks * 2, IDESC1, (c > 0) || (ks > 0));
            mma_commit(b ? bar1 : bar0);
        }
    }
    mbar_wait(bar0, cnt0 & 1); cnt0++;
    mbar_wait(bar1, cnt1 & 1); cnt1++;
    tc_fence_after();

    // ---------------- epilogue1 (8-warp split): D1 -> silu -> bf16 H in smem
    // upper half fires W2 chunk-0 cp.async first (waited at phase-2 sync)
    {
        if (tid >= 128) {
            int t0 = tid - 128;
            #pragma unroll
            for (int t = 0; t < 14; t++) {
                int e = t0 + t * 128;
                int r2 = e >> 3, g = e & 7;
                cp_async16(sb + SM_W2 + SW(r2 * 128 + g * 16),
                           g_W2T + (size_t)r2 * HID + g * 8);
            }
            cp_commit();
        }
        const int row = tid & 127;
        const int cb0 = (tid < 128) ? 0 : 4;
        unsigned regs[32];
        #pragma unroll 1
        for (int cb = cb0; cb < cb0 + 4; cb++) {
            ldtm32(regs, tmem + cb * 32);
            wait_ld();
            #pragma unroll
            for (int t = 0; t < 8; t++) {
                int n0 = cb * 32 + t * 4;
                float a0 = silu_f(__uint_as_float(regs[t * 4 + 0]) + sB1[n0 + 0]);
                float a1 = silu_f(__uint_as_float(regs[t * 4 + 1]) + sB1[n0 + 1]);
                float a2 = silu_f(__uint_as_float(regs[t * 4 + 2]) + sB1[n0 + 2]);
                float a3 = silu_f(__uint_as_float(regs[t * 4 + 3]) + sB1[n0 + 3]);
                uint2 w; w.x = f2bf2(a0, a1); w.y = f2bf2(a2, a3);
                unsigned off = row * 128 + ((n0 & 63) << 1);
                *(uint2*)(smem + SM_H + ((n0 >> 6) << 14) + SW(off)) = w;
            }
        }
        tc_fence_before();
        cp_wait0();
    }

    // ---------------- GEMM2: D2[128,224] = H[128,256] @ Wo2pad (D2 reuses D1 cols)
    // single smem buffer + register prefetch of next chunk during MMA
    #pragma unroll 1
    for (int q = 0; q < 4; q++) {
        fence_async_smem();
        __syncthreads();
        if (tid == 0) {
            if (q == 0) tc_fence_after();
            unsigned long long ad = mk_desc(sb + SM_H + q * 16384);
            unsigned long long bd = mk_desc(sb + SM_W2);
            #pragma unroll
            for (int ks = 0; ks < 4; ks++)
                mma_f16_ss(tmem, ad + ks * 2, bd + ks * 2, IDESC2, (q > 0) || (ks > 0));
            mma_commit(bar0);
        }
        if (q < 3) {
            uint4 wreg[7];
            #pragma unroll
            for (int t = 0; t < 7; t++) {
                int e = tid + t * NT;              // < 1792 exactly
                int r2 = e >> 3, g = e & 7;
                wreg[t] = *(const uint4*)(g_W2T + (size_t)r2 * HID + (q + 1) * 64 + g * 8);
            }
            mbar_wait(bar0, cnt0 & 1); cnt0++;     // MMA q done reading smem W2
            #pragma unroll
            for (int t = 0; t < 7; t++) {
                int e = tid + t * NT;
                int r2 = e >> 3, g = e & 7;
                *(uint4*)(smem + SM_W2 + SW(r2 * 128 + g * 16)) = wreg[t];
            }
        }
    }
    mbar_wait(bar0, cnt0 & 1); cnt0++;
    tc_fence_after();

    // ---------------- epilogue2 (8-warp split): D2 + bias -> sM [128][201] f32
    {
        const int row = tid & 127;
        float* rowM = (float*)(smem + SM_M) + row * 201;
        unsigned regs[32];
        const int cb0 = (tid < 128) ? 0 : 3;
        #pragma unroll 1
        for (int cb = cb0; cb < cb0 + 3; cb++) {
            ldtm32(regs, tmem + cb * 32);
            wait_ld();
            #pragma unroll
            for (int c = 0; c < 32; c++)
                rowM[cb * 32 + c] = __uint_as_float(regs[c]) + sB2[cb * 32 + c];
        }
        if (tid >= 128) {
            unsigned r0, r1, r2, r3;
            ldtm4(r0, r1, r2, r3, tmem + 192);
            wait_ld();
            rowM[192] = __uint_as_float(r0) + sB2[192];
            rowM[193] = __uint_as_float(r1) + sB2[193];
            rowM[194] = __uint_as_float(r2) + sB2[194];
            rowM[195] = __uint_as_float(r3) + sB2[195];
        }
        tc_fence_before();
    }
    __syncthreads();

    // ---------------- add overlap (float4-coalesced) ----------------
    {
        const float4* ovb4 = (const float4*)(overlap + (size_t)pbase * BB);  // 16B aligned
        float* sM = (float*)(smem + SM_M);
        #pragma unroll 1
        for (int t = 0; t < 25; t++) {
            int e = tid + t * NT;              // 6272 float4 total (49 per pair)
            if (e < TP * BB / 4) {
                float4 v = ovb4[e];
                int p = e / 49;
                int idx = (e - p * 49) * 4;
                float* dst = sM + p * 201 + idx;
                dst[0] += v.x; dst[1] += v.y; dst[2] += v.z; dst[3] += v.w;
            }
        }
    }
    __syncthreads();

    // ---------------- scatter: division-free, 2 threads per pair ------------
    {
        const float* sM = (const float*)(smem + SM_M);
        const int p = tid >> 1;
        const int half = tid & 1;
        const float* base = sM + p * 201;
        const int ib = sI[p] * Bb;
        const int jb = sJ[p] * Bb;
        // (i,j) blocks: each thread writes 7 rows x 7 float2 (contig 56B runs)
        #pragma unroll
        for (int r7 = 0; r7 < 7; r7++) {
            const int r = half * 7 + r7;
            const float* src = base + r * 14;
            float2* drow = (float2*)(out + (size_t)(ib + r) * NBdim + jb);
            #pragma unroll
            for (int c2 = 0; c2 < 7; c2++)
                drow[c2] = make_float2(src[c2 * 2], src[c2 * 2 + 1]);
        }
        // (j,i) transposed blocks: each thread writes 7 cols x 7 float2
        #pragma unroll
        for (int c7 = 0; c7 < 7; c7++) {
            const int cc = half * 7 + c7;
            const float* src = base + cc;
            float2* drow = (float2*)(out + (size_t)(jb + cc) * NBdim + ib);
            #pragma unroll
            for (int k = 0; k < 7; k++)
                drow[k] = make_float2(src[(2 * k) * 14], src[(2 * k + 1) * 14]);
        }
    }
    __syncthreads();
    if (tid < 32) tmem_dealloc(tmem, 256);
#endif  // HAS_TC (stub on non-'a' virtual pass; sm_103a cubin is what runs)
}

// ===========================================================================
// Diagonal kernel (tiny)
// ===========================================================================
__global__ void __launch_bounds__(256)
diag_kernel(const float* __restrict__ nodes, const float* __restrict__ edges,
            const float* __restrict__ ablk,
            const float* __restrict__ W1, const float* __restrict__ b1,
            const float* __restrict__ W2, const float* __restrict__ b2,
            float* __restrict__ out)
{
    __shared__ float sx[HID];
    __shared__ float sh[HID];
    const int i = blockIdx.x;
    const int tid = threadIdx.x;

    sx[tid] = (tid < Fdim) ? nodes[i * Fdim + tid]
                           : edges[((size_t)i * NA + i) * FEdim + (tid - Fdim)];
    __syncthreads();

    float acc = b1[tid];
    #pragma unroll 8
    for (int k = 0; k < HID; k++)
        acc = fmaf(sx[k], W1[k * HID + tid], acc);
    sh[tid] = silu_f(acc);
    __syncthreads();

    if (tid < BB) {
        float a2 = b2[tid];
        #pragma unroll 8
        for (int k = 0; k < HID; k++)
            a2 = fmaf(sh[k], W2[k * BB + tid], a2);
        int r = tid / Bb;
        int c = tid - r * Bb;
        out[(size_t)(i * Bb + r) * NBdim + i * Bb + c] = a2 + ablk[i * BB + tid];
    }
}

// ===========================================================================
extern "C" void kernel_launch(void* const* d_in, const int* in_sizes, int n_in,
                              void* d_out, int out_size)
{
    const float* nodes = (const float*)d_in[0];
    const float* edges = (const float*)d_in[1];
    const float* ablk  = (const float*)d_in[2];
    const float* ovlp  = (const float*)d_in[3];
    const float* W1    = (const float*)d_in[4];
    const float* b1    = (const float*)d_in[5];
    const float* W2    = (const float*)d_in[6];
    const float* b2    = (const float*)d_in[7];
    const float* Wo1   = (const float*)d_in[8];
    const float* bo1   = (const float*)d_in[9];
    const float* Wo2   = (const float*)d_in[10];
    const float* bo2   = (const float*)d_in[11];
    const int*   pi    = (const int*)d_in[12];
    const int*   pj    = (const int*)d_in[13];
    float* out = (float*)d_out;

    const int P = in_sizes[12];   // 130816 = 1022 * 128

    cudaFuncSetAttribute(off_tc_kernel, cudaFuncAttributeMaxDynamicSharedMemorySize, SMEM_TOTAL);

    // validated 3-launch configuration (281us baseline), off_tc last
    prep_kernel<<<148, 256>>>(Wo1, Wo2);
    diag_kernel<<<NA, 256>>>(nodes, edges, ablk, W1, b1, W2, b2, out);
    off_tc_kernel<<<P / TP, NT, SMEM_TOTAL>>>(nodes, edges, ovlp, bo1, bo2, pi, pj, out);
}

// round 15
// speedup vs baseline: 1.3659x; 1.3659x over previous
#include <cuda_runtime.h>
#include <cuda_bf16.h>
#include <cuda_fp16.h>

#define NA    512
#define Fdim  128
#define FEdim 128
#define HID   256
#define Bb    14
#define BB    196
#define NBdim 7168
#define TP    128          // pairs per CTA
#define NT    256
#define N2PAD 224          // padded GEMM2 N (196 -> 224)

// -------- arch-feature detection: tcgen05 only exists on the 'a' target ----
#if defined(__CUDA_ARCH__) && \
    (defined(__CUDA_ARCH_FEAT_SM103_ALL) || \
     (defined(__CUDA_ARCH_SPECIFIC__) && (__CUDA_ARCH_SPECIFIC__ == 1030)) || \
     (defined(__CUDA_ARCH_FAMILY_SPECIFIC__) && (__CUDA_ARCH_FAMILY_SPECIFIC__ == 1030)))
#define HAS_TC 1
#else
#define HAS_TC 0
#endif

// ---------------- device scratch ----------------
__device__ __align__(16) __nv_bfloat16 g_W1T[HID * 384];     // [256][384] bf16
__device__ __align__(16) __half        g_W2T[N2PAD * HID];   // [224][256] f16

// ---------------- smem byte offsets (~104KB -> 2 CTAs/SM) ----------------
#define SM_X0    0         // X chunk buf0  [128][64]bf16 = 16384
#define SM_X1    16384
#define SM_W0    32768     // W1 chunk buf0 [256][64]bf16 = 32768
#define SM_W1    65536     // W1 chunk buf1
#define SM_H     0         // H [128][256]f16, 4 chunk-blocks of 16384
#define SM_W2    65536     // W2 chunk [224][64]f16 = 28672, single buf
#define SM_M     0         // sM [128][201] f32 = 102912
#define SM_BARS  102912    // +0 tmem ptr, +8 bar0, +16 bar1
#define SM_B1    102944    // bo1 256 f32
#define SM_B2    103968    // bo2 padded 224 f32
#define SM_IJ    104864    // 128 i + 128 j int
#define SMEM_TOTAL 105984

#define SW(o) ((o) ^ (((o) >> 3) & 0x70))

// idesc: dtype=F32, K-major, M=128
#define IDESC1 ((1u<<4)|(1u<<7)|(1u<<10)|((HID/8)<<17)|((128/16)<<24))    // bf16 x bf16, N=256
#define IDESC2 ((1u<<4)|((N2PAD/8)<<17)|((128/16)<<24))                   // f16 x f16,  N=224

// ---------------- generic helpers ----------------
__device__ __forceinline__ float silu_f(float x) { return x / (1.0f + __expf(-x)); }
__device__ __forceinline__ unsigned f2bf2(float lo, float hi) {
    __nv_bfloat162 h = __floats2bfloat162_rn(lo, hi);
    return *(unsigned*)&h;
}
__device__ __forceinline__ unsigned smem_u32(const void* p) {
    unsigned a;
    asm("{ .reg .u64 t; cvta.to.shared.u64 t, %1; cvt.u32.u64 %0, t; }" : "=r"(a) : "l"(p));
    return a;
}
// ---- packed fp16 silu helpers (MUFU-lean path) ----
__device__ __forceinline__ unsigned cvt_f16x2(float hi, float lo) {
    unsigned r;
    asm("cvt.rn.f16x2.f32 %0, %1, %2;" : "=r"(r) : "f"(hi), "f"(lo));
    return r;
}
__device__ __forceinline__ unsigned tanh_h2(unsigned x) {
    unsigned r;
    asm("tanh.approx.f16x2 %0, %1;" : "=r"(r) : "r"(x));
    return r;
}
__device__ __forceinline__ unsigned hmul2u(unsigned a, unsigned b) {
    unsigned r;
    asm("mul.rn.f16x2 %0, %1, %2;" : "=r"(r) : "r"(a), "r"(b));
    return r;
}
__device__ __forceinline__ unsigned hfma2u(unsigned a, unsigned b, unsigned c) {
    unsigned r;
    asm("fma.rn.f16x2 %0, %1, %2, %3;" : "=r"(r) : "r"(a), "r"(b), "r"(c));
    return r;
}
#define H2_HALF 0x38003800u   // half2(0.5, 0.5)
// silu for a packed f16x2 pair: x * (0.5 + 0.5*tanh(x/2)); 1 MUFU per 2 elems
__device__ __forceinline__ unsigned silu_h2(unsigned xp) {
    unsigned t = tanh_h2(hmul2u(xp, H2_HALF));
    unsigned s = hfma2u(t, H2_HALF, H2_HALF);
    return hmul2u(xp, s);
}

#if HAS_TC
// ---------------- tcgen05 PTX helpers (only on the 'a' target) ----
__device__ __forceinline__ unsigned long long mk_desc(unsigned addr) {
    const unsigned long long base =
        (2ull << 61) | (1ull << 46) | (64ull << 32) | (1ull << 16);   // SW128, LBO=1, SBO=64
    return base | ((unsigned long long)(addr >> 4) & 0x3FFF);
}
__device__ __forceinline__ void mma_f16_ss(unsigned d, unsigned long long a,
                                           unsigned long long b, unsigned idesc, bool acc) {
    unsigned e = acc ? 1u : 0u;
    asm volatile(
        "{\n\t.reg .pred p;\n\t"
        "setp.ne.u32 p, %5, 0;\n\t"
        "tcgen05.mma.cta_group::1.kind::f16 [%0], %1, %2, %3, {%4,%4,%4,%4}, p;\n\t}"
        :: "r"(d), "l"(a), "l"(b), "r"(idesc), "r"(0u), "r"(e) : "memory");
}
__device__ __forceinline__ void tmem_alloc(unsigned smem_addr, unsigned ncols) {
    asm volatile("tcgen05.alloc.cta_group::1.sync.aligned.shared::cta.b32 [%0], %1;"
                 :: "r"(smem_addr), "r"(ncols) : "memory");
}
__device__ __forceinline__ void tmem_dealloc(unsigned tmem, unsigned ncols) {
    asm volatile("tcgen05.dealloc.cta_group::1.sync.aligned.b32 %0, %1;" :: "r"(tmem), "r"(ncols));
}
__device__ __forceinline__ void tmem_relinquish() {
    asm volatile("tcgen05.relinquish_alloc_permit.cta_group::1.sync.aligned;");
}
__device__ __forceinline__ void mbar_init(unsigned addr, unsigned cnt) {
    asm volatile("mbarrier.init.shared.b64 [%0], %1;" :: "r"(addr), "r"(cnt) : "memory");
}
__device__ __forceinline__ void mbar_wait(unsigned addr, unsigned parity) {
    asm volatile(
        "{\n\t.reg .pred P1;\n\t"
        "W%=:\n\t"
        "mbarrier.try_wait.parity.acquire.cta.shared::cta.b64 P1, [%0], %1, 0x989680;\n\t"
        "@P1 bra.uni D%=;\n\t"
        "bra.uni W%=;\n\t"
        "D%=:\n\t}"
        :: "r"(addr), "r"(parity) : "memory");
}
__device__ __forceinline__ void mma_commit(unsigned bar) {
    asm volatile("tcgen05.commit.cta_group::1.mbarrier::arrive::one.shared::cluster.b64 [%0];"
                 :: "r"(bar) : "memory");
}
__device__ __forceinline__ void fence_async_smem() {
    asm volatile("fence.proxy.async.shared::cta;" ::: "memory");
}
__device__ __forceinline__ void tc_fence_after() {
    asm volatile("tcgen05.fence::after_thread_sync;" ::: "memory");
}
__device__ __forceinline__ void tc_fence_before() {
    asm volatile("tcgen05.fence::before_thread_sync;" ::: "memory");
}
__device__ __forceinline__ void wait_ld() {
    asm volatile("tcgen05.wait::ld.sync.aligned;" ::: "memory");
}
__device__ __forceinline__ void ldtm32(unsigned* r, unsigned addr) {
    asm volatile(
        "tcgen05.ld.sync.aligned.32x32b.x32.b32 "
        "{%0,%1,%2,%3,%4,%5,%6,%7,%8,%9,%10,%11,%12,%13,%14,%15,"
        "%16,%17,%18,%19,%20,%21,%22,%23,%24,%25,%26,%27,%28,%29,%30,%31}, [%32];"
        : "=r"(r[0]),"=r"(r[1]),"=r"(r[2]),"=r"(r[3]),"=r"(r[4]),"=r"(r[5]),"=r"(r[6]),"=r"(r[7]),
          "=r"(r[8]),"=r"(r[9]),"=r"(r[10]),"=r"(r[11]),"=r"(r[12]),"=r"(r[13]),"=r"(r[14]),"=r"(r[15]),
          "=r"(r[16]),"=r"(r[17]),"=r"(r[18]),"=r"(r[19]),"=r"(r[20]),"=r"(r[21]),"=r"(r[22]),"=r"(r[23]),
          "=r"(r[24]),"=r"(r[25]),"=r"(r[26]),"=r"(r[27]),"=r"(r[28]),"=r"(r[29]),"=r"(r[30]),"=r"(r[31])
        : "r"(addr));
}
__device__ __forceinline__ void ldtm4(unsigned& a, unsigned& b, unsigned& c, unsigned& d, unsigned addr) {
    asm volatile("tcgen05.ld.sync.aligned.32x32b.x4.b32 {%0,%1,%2,%3}, [%4];"
                 : "=r"(a), "=r"(b), "=r"(c), "=r"(d) : "r"(addr));
}
#endif  // HAS_TC

// ===========================================================================
// prep: transpose + convert weights into device scratch (W1->bf16, W2->f16)
// ===========================================================================
__global__ void prep_kernel(const float* __restrict__ Wo1, const float* __restrict__ Wo2) {
    int stride = gridDim.x * blockDim.x;
    int t = blockIdx.x * blockDim.x + threadIdx.x;
    for (int e = t; e < HID * 384; e += stride) {
        int n = e / 384, k = e - n * 384;
        g_W1T[e] = __float2bfloat16(Wo1[k * HID + n]);
    }
    for (int e = t; e < N2PAD * HID; e += stride) {
        int n = e / HID, k = e - n * HID;
        g_W2T[e] = (n < BB) ? __float2half(Wo2[k * BB + n]) : __float2half(0.0f);
    }
}

// ===========================================================================
// Off-diagonal tcgen05 kernel: 128 pairs per CTA, 2 CTAs per SM
// ===========================================================================
__global__ void __launch_bounds__(NT, 2)
off_tc_kernel(const float* __restrict__ nodes, const float* __restrict__ edges,
              const float* __restrict__ overlap,
              const float* __restrict__ bo1, const float* __restrict__ bo2,
              const int* __restrict__ pi, const int* __restrict__ pj,
              float* __restrict__ out)
{
#if HAS_TC
    extern __shared__ char smem[];
    const unsigned sb = smem_u32(smem);
    const int tid = threadIdx.x;
    const int pbase = blockIdx.x * TP;

    int*   sI  = (int*)(smem + SM_IJ);
    int*   sJ  = sI + TP;
    float* sB1 = (float*)(smem + SM_B1);
    float* sB2 = (float*)(smem + SM_B2);

    if (tid < TP) { sI[tid] = pi[pbase + tid]; sJ[tid] = pj[pbase + tid]; }
    sB1[tid] = bo1[tid];
    if (tid < N2PAD) sB2[tid] = (tid < BB) ? bo2[tid] : 0.0f;

    if (tid == 0) {
        mbar_init(sb + SM_BARS + 8, 1);
        mbar_init(sb + SM_BARS + 16, 1);
    }
    if (tid < 32) {
        tmem_alloc(sb + SM_BARS, 256);   // D1 0..255; D2 reuses 0..223
        tmem_relinquish();
    }
    __syncthreads();

    unsigned tmem;
    asm volatile("ld.shared.b32 %0, [%1];" : "=r"(tmem) : "r"(sb + SM_BARS));
    const unsigned bar0 = sb + SM_BARS + 8;
    const unsigned bar1 = sb + SM_BARS + 16;
    int cnt0 = 0, cnt1 = 0;

    // gather mapping: 8 lanes per pair-row segment (coalesced 32B/lane)
    const int gseg = tid & 7;
    const int grow0 = tid >> 3;

    // ---------------- GEMM1: D1[128,256] = X[128,384] @ Wo1, K chunks of 64
    #pragma unroll 1
    for (int c = 0; c < 6; c++) {
        const int b = c & 1;
        if (c >= 2) {
            if (b == 0) { mbar_wait(bar0, cnt0 & 1); cnt0++; }
            else        { mbar_wait(bar1, cnt1 & 1); cnt1++; }
        }
        // X chunk gather+convert -> swizzled smem [128][64]bf16 (coalesced)
        {
            char* xdst = smem + (b ? SM_X1 : SM_X0);
            #pragma unroll
            for (int it = 0; it < 4; it++) {
                const int p = grow0 + it * 32;
                const int xi = sI[p], xj = sJ[p];
                const float* s;
                if (c < 2)      s = nodes + (size_t)xi * Fdim + c * 64;
                else if (c < 4) s = nodes + (size_t)xj * Fdim + (c - 2) * 64;
                else            s = edges + ((size_t)xi * NA + xj) * FEdim + (c - 4) * 64;
                s += gseg * 8;
                float4 v0 = *(const float4*)(s);
                float4 v1 = *(const float4*)(s + 4);
                uint4 w;
                w.x = f2bf2(v0.x, v0.y); w.y = f2bf2(v0.z, v0.w);
                w.z = f2bf2(v1.x, v1.y); w.w = f2bf2(v1.z, v1.w);
                *(uint4*)(xdst + SW(p * 128 + gseg * 16)) = w;
            }
        }
        // W1 chunk [256][64]bf16 -> swizzled smem (index-linear, coalesced)
        {
            char* wdst = smem + (b ? SM_W1 : SM_W0);
            #pragma unroll
            for (int t = 0; t < 8; t++) {
                int e = tid + t * NT;         // 0..2047
                int row = e >> 3, g = e & 7;
                uint4 v = *(const uint4*)(g_W1T + (size_t)row * 384 + c * 64 + g * 8);
                *(uint4*)(wdst + SW(row * 128 + g * 16)) = v;
            }
        }
        fence_async_smem();
        __syncthreads();
        if (tid == 0) {
            unsigned long long ad = mk_desc(sb + (b ? SM_X1 : SM_X0));
            unsigned long long bd = mk_desc(sb + (b ? SM_W1 : SM_W0));
            #pragma unroll
            for (int ks = 0; ks < 4; ks++)
                mma_f16_ss(tmem, ad + ks * 2, bd + ks * 2, IDESC1, (c > 0) || (ks > 0));
            mma_commit(b ? bar1 : bar0);
        }
    }
    mbar_wait(bar0, cnt0 & 1); cnt0++;
    mbar_wait(bar1, cnt1 & 1); cnt1++;
    tc_fence_after();

    // ---------------- epilogue1 (8-warp split): D1 -> silu (f16x2 tanh) -> H
    {
        const int row = tid & 127;
        const int cb0 = (tid < 128) ? 0 : 4;
        unsigned regs[32];
        #pragma unroll 1
        for (int cb = cb0; cb < cb0 + 4; cb++) {
            ldtm32(regs, tmem + cb * 32);
            wait_ld();
            #pragma unroll
            for (int t = 0; t < 8; t++) {
                int n0 = cb * 32 + t * 4;
                float a0 = __uint_as_float(regs[t * 4 + 0]) + sB1[n0 + 0];
                float a1 = __uint_as_float(regs[t * 4 + 1]) + sB1[n0 + 1];
                float a2 = __uint_as_float(regs[t * 4 + 2]) + sB1[n0 + 2];
                float a3 = __uint_as_float(regs[t * 4 + 3]) + sB1[n0 + 3];
                uint2 w;
                w.x = silu_h2(cvt_f16x2(a1, a0));   // lo=silu(a0), hi=silu(a1)
                w.y = silu_h2(cvt_f16x2(a3, a2));
                unsigned off = row * 128 + ((n0 & 63) << 1);
                *(uint2*)(smem + SM_H + ((n0 >> 6) << 14) + SW(off)) = w;
            }
        }
        tc_fence_before();
        if (tid < 128) {
            // W2 chunk 0 -> smem (1792 uint4 = 14 * 128), f16
            #pragma unroll
            for (int t = 0; t < 14; t++) {
                int e = tid + t * 128;
                int r2 = e >> 3, g = e & 7;
                uint4 v = *(const uint4*)(g_W2T + (size_t)r2 * HID + g * 8);
                *(uint4*)(smem + SM_W2 + SW(r2 * 128 + g * 16)) = v;
            }
        }
    }

    // ---------------- GEMM2: D2[128,224] = H[128,256] @ Wo2pad (f16 x f16)
    // single smem buffer + register prefetch of next chunk during MMA
    #pragma unroll 1
    for (int q = 0; q < 4; q++) {
        fence_async_smem();
        __syncthreads();
        if (tid == 0) {
            if (q == 0) tc_fence_after();
            unsigned long long ad = mk_desc(sb + SM_H + q * 16384);
            unsigned long long bd = mk_desc(sb + SM_W2);
            #pragma unroll
            for (int ks = 0; ks < 4; ks++)
                mma_f16_ss(tmem, ad + ks * 2, bd + ks * 2, IDESC2, (q > 0) || (ks > 0));
            mma_commit(bar0);
        }
        if (q < 3) {
            uint4 wreg[7];
            #pragma unroll
            for (int t = 0; t < 7; t++) {
                int e = tid + t * NT;              // < 1792 exactly
                int r2 = e >> 3, g = e & 7;
                wreg[t] = *(const uint4*)(g_W2T + (size_t)r2 * HID + (q + 1) * 64 + g * 8);
            }
            mbar_wait(bar0, cnt0 & 1); cnt0++;     // MMA q done reading smem W2
            #pragma unroll
            for (int t = 0; t < 7; t++) {
                int e = tid + t * NT;
                int r2 = e >> 3, g = e & 7;
                *(uint4*)(smem + SM_W2 + SW(r2 * 128 + g * 16)) = wreg[t];
            }
        }
    }
    mbar_wait(bar0, cnt0 & 1); cnt0++;
    tc_fence_after();

    // ---------------- epilogue2 (8-warp split): D2 + bias -> sM [128][201] f32
    {
        const int row = tid & 127;
        float* rowM = (float*)(smem + SM_M) + row * 201;
        unsigned regs[32];
        const int cb0 = (tid < 128) ? 0 : 3;
        #pragma unroll 1
        for (int cb = cb0; cb < cb0 + 3; cb++) {
            ldtm32(regs, tmem + cb * 32);
            wait_ld();
            #pragma unroll
            for (int c = 0; c < 32; c++)
                rowM[cb * 32 + c] = __uint_as_float(regs[c]) + sB2[cb * 32 + c];
        }
        if (tid >= 128) {
            unsigned r0, r1, r2, r3;
            ldtm4(r0, r1, r2, r3, tmem + 192);
            wait_ld();
            rowM[192] = __uint_as_float(r0) + sB2[192];
            rowM[193] = __uint_as_float(r1) + sB2[193];
            rowM[194] = __uint_as_float(r2) + sB2[194];
            rowM[195] = __uint_as_float(r3) + sB2[195];
        }
        tc_fence_before();
    }
    __syncthreads();

    // ---------------- add overlap (float4-coalesced) ----------------
    {
        const float4* ovb4 = (const float4*)(overlap + (size_t)pbase * BB);  // 16B aligned
        float* sM = (float*)(smem + SM_M);
        #pragma unroll 1
        for (int t = 0; t < 25; t++) {
            int e = tid + t * NT;              // 6272 float4 total (49 per pair)
            if (e < TP * BB / 4) {
                float4 v = ovb4[e];
                int p = e / 49;
                int idx = (e - p * 49) * 4;
                float* dst = sM + p * 201 + idx;
                dst[0] += v.x; dst[1] += v.y; dst[2] += v.z; dst[3] += v.w;
            }
        }
    }
    __syncthreads();

    // ---------------- scatter: p-major float2 stores, exact counts ----------
    {
        const float* sM = (const float*)(smem + SM_M);
        // (i,j) blocks: 12544 float2 = 49 * NT; run = 7 float2 per (p,r)
        #pragma unroll 1
        for (int t = 0; t < 49; t++) {
            int e = tid + t * NT;
            int p = e / 98;
            int q2 = e - p * 98;
            int r = q2 / 7;
            int c2 = q2 - r * 7;
            const float* src = sM + p * 201 + r * 14 + c2 * 2;
            float2 v = make_float2(src[0], src[1]);
            *(float2*)(out + (size_t)(sI[p] * Bb + r) * NBdim + sJ[p] * Bb + c2 * 2) = v;
        }
        // (j,i) transposed blocks: runs along r
        #pragma unroll 1
        for (int t = 0; t < 49; t++) {
            int e = tid + t * NT;
            int p = e / 98;
            int q2 = e - p * 98;
            int c = q2 / 7;
            int k = q2 - c * 7;
            const float* src = sM + p * 201 + (2 * k) * 14 + c;
            float2 v = make_float2(src[0], src[14]);
            *(float2*)(out + (size_t)(sJ[p] * Bb + c) * NBdim + sI[p] * Bb + 2 * k) = v;
        }
    }
    __syncthreads();
    if (tid < 32) tmem_dealloc(tmem, 256);
#endif  // HAS_TC (stub on non-'a' virtual pass; sm_103a cubin is what runs)
}

// ===========================================================================
// Diagonal kernel (tiny)
// ===========================================================================
__global__ void __launch_bounds__(256)
diag_kernel(const float* __restrict__ nodes, const float* __restrict__ edges,
            const float* __restrict__ ablk,
            const float* __restrict__ W1, const float* __restrict__ b1,
            const float* __restrict__ W2, const float* __restrict__ b2,
            float* __restrict__ out)
{
    __shared__ float sx[HID];
    __shared__ float sh[HID];
    const int i = blockIdx.x;
    const int tid = threadIdx.x;

    sx[tid] = (tid < Fdim) ? nodes[i * Fdim + tid]
                           : edges[((size_t)i * NA + i) * FEdim + (tid - Fdim)];
    __syncthreads();

    float acc = b1[tid];
    #pragma unroll 8
    for (int k = 0; k < HID; k++)
        acc = fmaf(sx[k], W1[k * HID + tid], acc);
    sh[tid] = silu_f(acc);
    __syncthreads();

    if (tid < BB) {
        float a2 = b2[tid];
        #pragma unroll 8
        for (int k = 0; k < HID; k++)
            a2 = fmaf(sh[k], W2[k * BB + tid], a2);
        int r = tid / Bb;
        int c = tid - r * Bb;
        out[(size_t)(i * Bb + r) * NBdim + i * Bb + c] = a2 + ablk[i * BB + tid];
    }
}

// ===========================================================================
extern "C" void kernel_launch(void* const* d_in, const int* in_sizes, int n_in,
                              void* d_out, int out_size)
{
    const float* nodes = (const float*)d_in[0];
    const float* edges = (const float*)d_in[1];
    const float* ablk  = (const float*)d_in[2];
    const float* ovlp  = (const float*)d_in[3];
    const float* W1    = (const float*)d_in[4];
    const float* b1    = (const float*)d_in[5];
    const float* W2    = (const float*)d_in[6];
    const float* b2    = (const float*)d_in[7];
    const float* Wo1   = (const float*)d_in[8];
    const float* bo1   = (const float*)d_in[9];
    const float* Wo2   = (const float*)d_in[10];
    const float* bo2   = (const float*)d_in[11];
    const int*   pi    = (const int*)d_in[12];
    const int*   pj    = (const int*)d_in[13];
    float* out = (float*)d_out;

    const int P = in_sizes[12];   // 130816 = 1022 * 128

    cudaFuncSetAttribute(off_tc_kernel, cudaFuncAttributeMaxDynamicSharedMemorySize, SMEM_TOTAL);

    // validated 3-launch configuration (281us baseline), off_tc last
    prep_kernel<<<148, 256>>>(Wo1, Wo2);
    diag_kernel<<<NA, 256>>>(nodes, edges, ablk, W1, b1, W2, b2, out);
    off_tc_kernel<<<P / TP, NT, SMEM_TOTAL>>>(nodes, edges, ovlp, bo1, bo2, pi, pj, out);
}